// round 7
// baseline (speedup 1.0000x reference)
#include <cuda_runtime.h>
#include <cuda_fp16.h>
#include <math.h>
#include <stdint.h>

// ============================================================================
// EdgeDecoder, HMMA m16n8k16 fp16 single-term (fp32 accum).
// Round 7: persistent CTAs, A-slot parity pipelining (next-tile gathers hidden
// under GEMM2/epi2), double-buffered indices, warm tile-boundary prefetch.
// ============================================================================

#define NTH 256

// packed fp16 weights, fragment order:
// [type][ks][ntpair8][lane32][w4]  w: {nt_even b0, nt_even b1, nt_odd b0, nt_odd b1}
__device__ __align__(128) uint32_t g_wbi_pack[32768];   // 2 x 16ks x 8 x 32 x 4
__device__ __align__(128) uint32_t g_w1_pack[16384];    // 2 x 8ks  x 8 x 32 x 4

// ---- SMEM layout (bytes) ----
constexpr int OFF_A    = 0;         // A frag slots [mt8][slot16]*512 = 65536
constexpr int OFF_RING = 65536;     // 2 x 16384 weight chunk ring
constexpr int OFF_SOFF = 98304;     // 2 x u32[256] (double-buffered row offsets)
constexpr int OFF_BBI  = 100352;    // f32[128]
constexpr int OFF_B1   = 100864;
constexpr int OFF_W2   = 101376;
constexpr int OFF_PART = 101888;    // f32[256]
constexpr int SMEM_TOTAL = 102912;

#define CPA(dst, src) \
    asm volatile("cp.async.cg.shared.global [%0], [%1], 16;" :: "r"(dst), "l"(src))
#define CPA_COMMIT() asm volatile("cp.async.commit_group;" ::: "memory")
#define CPA_WAIT(n)  asm volatile("cp.async.wait_group %0;" :: "n"(n) : "memory")

__device__ __forceinline__ uint32_t smem_to_u32(const void* p) {
    uint32_t a;
    asm("{ .reg .u64 t; cvta.to.shared.u64 t, %1; cvt.u32.u64 %0, t; }" : "=r"(a) : "l"(p));
    return a;
}

__device__ __forceinline__ void mma_f16(float c[4], const uint32_t a[4],
                                        uint32_t b0, uint32_t b1) {
    asm volatile(
        "mma.sync.aligned.m16n8k16.row.col.f32.f16.f16.f32 "
        "{%0,%1,%2,%3}, {%4,%5,%6,%7}, {%8,%9}, {%0,%1,%2,%3};"
        : "+f"(c[0]), "+f"(c[1]), "+f"(c[2]), "+f"(c[3])
        : "r"(a[0]), "r"(a[1]), "r"(a[2]), "r"(a[3]), "r"(b0), "r"(b1));
}

__device__ __forceinline__ float eluf(float x) { return x > 0.f ? x : (__expf(x) - 1.f); }

__device__ __forceinline__ uint32_t pack_h2(float a, float b) {
    __half2 h = __floats2half2_rn(a, b);
    return *(uint32_t*)&h;
}

// ============================================================================
// Pre-pack: fp32 weights -> fp16 frag-order lines, 2 nt per 16B line.
// ============================================================================
__global__ void pack_weights_kernel(
    const float* __restrict__ Wbi_ui, const float* __restrict__ W1_ui,
    const float* __restrict__ Wbi_iu, const float* __restrict__ W1_iu)
{
    int id = blockIdx.x * blockDim.x + threadIdx.x;
    const float* W;
    uint32_t* dst;
    int w, lane, ntp, ks;
    if (id < 32768) {
        w = id & 3; lane = (id >> 2) & 31; ntp = (id >> 7) & 7;
        ks = (id >> 10) & 15;
        int type = (id >> 14) & 1;
        W = type ? Wbi_iu : Wbi_ui;
        dst = g_wbi_pack + id;
    } else {
        int id2 = id - 32768;
        if (id2 >= 16384) return;
        w = id2 & 3; lane = (id2 >> 2) & 31; ntp = (id2 >> 7) & 7;
        ks = (id2 >> 10) & 7;
        int type = (id2 >> 13) & 1;
        W = type ? W1_iu : W1_ui;
        dst = g_w1_pack + id2;
    }
    int nt = ntp * 2 + (w >> 1), r = w & 1;
    int k = ks * 16 + (lane & 3) * 2 + r * 8;
    int n = nt * 8 + (lane >> 2);
    *dst = pack_h2(W[k * 128 + n], W[(k + 1) * 128 + n]);
}

// one ks step for one warp: 2 A LDS.128 + 4 B LDS.128 + 16 HMMA
__device__ __forceinline__ void mma_step(
    const char* smA, const char* smB_ks, int slotA, int mi, int ni, int l16,
    float C[2][8][4])
{
    uint4 A0 = *(const uint4*)(smA + ((mi * 2 + 0) * 16 + slotA) * 512 + l16);
    uint4 A1 = *(const uint4*)(smA + ((mi * 2 + 1) * 16 + slotA) * 512 + l16);
    #pragma unroll
    for (int p = 0; p < 4; p++) {
        uint4 B = *(const uint4*)(smB_ks + (ni * 4 + p) * 512 + l16);
        mma_f16(C[0][2 * p],     &A0.x, B.x, B.y);
        mma_f16(C[1][2 * p],     &A1.x, B.x, B.y);
        mma_f16(C[0][2 * p + 1], &A0.x, B.z, B.w);
        mma_f16(C[1][2 * p + 1], &A1.x, B.z, B.w);
    }
}

__device__ __forceinline__ void issue_chunk(
    uint32_t ring_u32, int c, const uint32_t* wbiP, const uint32_t* w1P, int tid)
{
    const uint32_t* src = (c < 4) ? (wbiP + c * 4096) : (w1P + (c - 4) * 4096);
    uint32_t dst = ring_u32 + (uint32_t)(c & 1) * 16384;
    #pragma unroll
    for (int q = 0; q < 4; q++)
        CPA(dst + (uint32_t)(tid + q * 256) * 16, src + (tid + q * 256) * 4);
    CPA_COMMIT();
}

// gather one 128-K half for all 128 edges into A slots [slotbase..slotbase+7]
__device__ __forceinline__ void gather_half(
    char* smA, const float* eb, const uint32_t* sOffH, int slotbase,
    int wid, int lane, int l16)
{
    const int g = lane >> 2, t = lane & 3;
    const int mt = wid;
    const uint32_t o0 = sOffH[mt * 16 + g];
    const uint32_t o1 = sOffH[mt * 16 + g + 8];
    #pragma unroll
    for (int ks = 0; ks < 8; ks++) {
        const int kf = ks * 16 + 2 * t;
        float2 p00 = *(const float2*)(eb + o0 + kf);
        float2 p01 = *(const float2*)(eb + o0 + kf + 8);
        float2 p10 = *(const float2*)(eb + o1 + kf);
        float2 p11 = *(const float2*)(eb + o1 + kf + 8);
        uint4 hi;
        hi.x = pack_h2(p00.x, p00.y);
        hi.y = pack_h2(p10.x, p10.y);
        hi.z = pack_h2(p01.x, p01.y);
        hi.w = pack_h2(p11.x, p11.y);
        *(uint4*)(smA + (mt * 16 + slotbase + ks) * 512 + l16) = hi;
    }
}

__device__ __forceinline__ void compute_soff(
    uint32_t* sOffBuf, const void* ei, int base, int E, bool is64, int tid)
{
    const int half = tid >> 7, e = tid & 127, ge = base + e;
    uint32_t off = 0;
    if (ge < E) {
        long long idx = is64 ? ((const long long*)ei)[half ? (E + ge) : ge]
                             : (long long)((const int*)ei)[half ? (E + ge) : ge];
        off = (uint32_t)idx << 7;
    }
    sOffBuf[tid] = off;
}

__global__ __launch_bounds__(NTH, 2)
void edge_decoder_mma(
    const float* __restrict__ user_emb, const float* __restrict__ item_emb,
    const void* __restrict__ ei_ui, const void* __restrict__ ei_iu,
    const float* __restrict__ bbi_ui, const float* __restrict__ b1_ui,
    const float* __restrict__ W2_ui,  const float* __restrict__ b2_ui,
    const float* __restrict__ bbi_iu, const float* __restrict__ b1_iu,
    const float* __restrict__ W2_iu,  const float* __restrict__ b2_iu,
    float* __restrict__ out, int E)
{
    extern __shared__ char sm[];
    const uint32_t sm_u32 = smem_to_u32(sm);
    const int tid  = threadIdx.x;
    const int wid  = tid >> 5;
    const int lane = tid & 31;
    const int mi   = wid & 3;           // 32-row group (2 m16 tiles)
    const int ni   = wid >> 2;          // 64-col group (0..1)
    const int g    = lane >> 2;
    const int t    = lane & 3;
    const int l16  = lane * 16;

    constexpr int CPT = 148;            // CTAs per type
    const int type  = blockIdx.x & 1;
    const int slot0 = blockIdx.x >> 1;

    const float* srcE = type ? item_emb : user_emb;
    const float* dstE = type ? user_emb : item_emb;
    const void*  ei   = type ? ei_iu : ei_ui;
    const float* bbi  = type ? bbi_iu : bbi_ui;
    const float* b1   = type ? b1_iu : b1_ui;
    const float* W2   = type ? W2_iu : W2_ui;
    const float* b2   = type ? b2_iu : b2_ui;
    const uint32_t* wbiP = g_wbi_pack + (size_t)type * 16384;
    const uint32_t* w1P  = g_w1_pack  + (size_t)type * 8192;

    float*    sBbi  = (float*)(sm + OFF_BBI);
    float*    sB1   = (float*)(sm + OFF_B1);
    float*    sW2   = (float*)(sm + OFF_W2);
    float*    sPart = (float*)(sm + OFF_PART);
    uint32_t* sOff  = (uint32_t*)(sm + OFF_SOFF);   // 2 x 256
    char*     smA   = sm + OFF_A;
    char*     smRing = sm + OFF_RING;

    // ---- prologue: start weight stream, indices, biases, first gather ----
    issue_chunk(sm_u32 + OFF_RING, 0, wbiP, w1P, tid);
    issue_chunk(sm_u32 + OFF_RING, 1, wbiP, w1P, tid);

    bool is64;
    {
        const int* w = (const int*)ei_ui;
        int all0 = 1;
        #pragma unroll
        for (int k = 0; k < 8; k++) all0 &= (w[2 * k + 1] == 0);
        is64 = (all0 != 0);
    }
    const float b2v = b2[0];

    if (tid < 128) {
        sBbi[tid] = bbi[tid];
        sB1[tid]  = b1[tid];
        sW2[tid]  = W2[tid];
    }
    const int ntiles = (E + 127) / 128;
    compute_soff(sOff, ei, slot0 * 128, E, is64, tid);
    __syncthreads();                                   // sOff0 ready

    // first tile gather (parity 0: src -> slots 0..7, dst -> slots 8..15)
    gather_half(smA, srcE, sOff,       0, wid, lane, l16);
    gather_half(smA, dstE, sOff + 128, 8, wid, lane, l16);

    int it = 0;
    for (int tile = slot0; tile < ntiles; tile += CPT, it ^= 1) {
        const int base = tile * 128;
        const int poff = it ? 8 : 0;                   // this tile's slot offset
        const uint32_t* sOffNext = sOff + (it ? 0 : 256);

        // ---- GEMM1: 4 chunks x 4 ks ----
        float C[2][8][4];
        #pragma unroll
        for (int m = 0; m < 2; m++)
            #pragma unroll
            for (int a = 0; a < 8; a++)
                #pragma unroll
                for (int b = 0; b < 4; b++) C[m][a][b] = 0.f;

        #pragma unroll
        for (int c = 0; c < 4; c++) {
            CPA_WAIT(1);
            __syncthreads();                           // chunk c + A visible
            const char* bb = smRing + (c & 1) * 16384;
            #pragma unroll
            for (int klc = 0; klc < 4; klc++)
                mma_step(smA, bb + klc * 4096, (c * 4 + klc + poff) & 15,
                         mi, ni, l16, C);
            __syncthreads();                           // buf (c&1) reusable
            issue_chunk(sm_u32 + OFF_RING, c + 2, wbiP, w1P, tid);
            if (c == 0)                                // next-tile indices, hidden
                compute_soff((uint32_t*)sOffNext, ei, (tile + CPT) * 128, E, is64, tid);
        }

        // ---- epilogue1: ELU(C+bbi) -> fp16 -> A2 slots (poff + 0..7) ----
        #pragma unroll
        for (int mtl = 0; mtl < 2; mtl++) {
            #pragma unroll
            for (int s = 0; s < 4; s++) {
                uint4 hi;
                int col = ni * 64 + (2 * s) * 8 + 2 * t;
                {
                    const float bb0 = sBbi[col], bb1 = sBbi[col + 1];
                    hi.x = pack_h2(eluf(C[mtl][2 * s][0] + bb0), eluf(C[mtl][2 * s][1] + bb1));
                    hi.y = pack_h2(eluf(C[mtl][2 * s][2] + bb0), eluf(C[mtl][2 * s][3] + bb1));
                }
                col += 8;
                {
                    const float bb0 = sBbi[col], bb1 = sBbi[col + 1];
                    hi.z = pack_h2(eluf(C[mtl][2 * s + 1][0] + bb0), eluf(C[mtl][2 * s + 1][1] + bb1));
                    hi.w = pack_h2(eluf(C[mtl][2 * s + 1][2] + bb0), eluf(C[mtl][2 * s + 1][3] + bb1));
                }
                const int mt2 = mi * 2 + mtl;
                *(uint4*)(smA + (mt2 * 16 + poff + ni * 4 + s) * 512 + l16) = hi;
            }
        }

        // ---- hidden: next tile src-half gather into dead A1 slots ----
        gather_half(smA, srcE, sOffNext, 8 - poff, wid, lane, l16);

        // ---- GEMM2: chunks 4,5 (W1), A2 slots poff+0..7 ----
        float C2[2][8][4];
        #pragma unroll
        for (int m = 0; m < 2; m++)
            #pragma unroll
            for (int a = 0; a < 8; a++)
                #pragma unroll
                for (int b = 0; b < 4; b++) C2[m][a][b] = 0.f;

        CPA_WAIT(1);
        __syncthreads();                               // chunk 4 + A2 visible
        #pragma unroll
        for (int klc = 0; klc < 4; klc++)
            mma_step(smA, smRing + klc * 4096, poff + klc, mi, ni, l16, C2);
        CPA_WAIT(0);
        __syncthreads();                               // chunk 5 visible
        #pragma unroll
        for (int klc = 0; klc < 4; klc++)
            mma_step(smA, smRing + 16384 + klc * 4096, poff + 4 + klc, mi, ni, l16, C2);

        // ---- epilogue2: ELU(C2+b1) . W2, quad reduce ----
        #pragma unroll
        for (int mtl = 0; mtl < 2; mtl++) {
            float r0 = 0.f, r1 = 0.f;
            #pragma unroll
            for (int ntl = 0; ntl < 8; ntl++) {
                const int col = ni * 64 + ntl * 8 + 2 * t;
                const float w0 = sW2[col], w1 = sW2[col + 1];
                const float bb0 = sB1[col], bb1 = sB1[col + 1];
                r0 += eluf(C2[mtl][ntl][0] + bb0) * w0 + eluf(C2[mtl][ntl][1] + bb1) * w1;
                r1 += eluf(C2[mtl][ntl][2] + bb0) * w0 + eluf(C2[mtl][ntl][3] + bb1) * w1;
            }
            r0 += __shfl_xor_sync(0xffffffffu, r0, 1);
            r1 += __shfl_xor_sync(0xffffffffu, r1, 1);
            r0 += __shfl_xor_sync(0xffffffffu, r0, 2);
            r1 += __shfl_xor_sync(0xffffffffu, r1, 2);
            if (t == 0) {
                const int m = (mi * 2 + mtl) * 16 + g;
                sPart[ni * 128 + m]     = r0;
                sPart[ni * 128 + m + 8] = r1;
            }
        }
        __syncthreads();                               // sPart ready; GEMM2 done

        if (tid < 128) {
            const int ge = base + tid;
            if (ge < E) {
                float s = sPart[tid] + sPart[128 + tid] + b2v;
                out[(size_t)type * E + ge] = 1.f / (1.f + __expf(-s));
            }
        }

        // ---- warm start for next tile: weights + dst-half gather ----
        issue_chunk(sm_u32 + OFF_RING, 0, wbiP, w1P, tid);
        issue_chunk(sm_u32 + OFF_RING, 1, wbiP, w1P, tid);
        gather_half(smA, dstE, sOffNext + 128, poff, wid, lane, l16);
        // next iteration's first chunk barrier orders these writes for readers
    }
    CPA_WAIT(0);                                       // drain before exit
}

extern "C" void kernel_launch(void* const* d_in, const int* in_sizes, int n_in,
                              void* d_out, int out_size) {
    (void)n_in; (void)out_size;
    const int E = in_sizes[2] / 2;
    pack_weights_kernel<<<96, 512>>>(
        (const float*)d_in[4], (const float*)d_in[6],
        (const float*)d_in[10], (const float*)d_in[12]);
    cudaFuncSetAttribute(edge_decoder_mma,
                         cudaFuncAttributeMaxDynamicSharedMemorySize, SMEM_TOTAL);
    edge_decoder_mma<<<296, NTH, SMEM_TOTAL>>>(
        (const float*)d_in[0],  (const float*)d_in[1],
        d_in[2], d_in[3],
        (const float*)d_in[5],  (const float*)d_in[7],
        (const float*)d_in[8],  (const float*)d_in[9],
        (const float*)d_in[11], (const float*)d_in[13],
        (const float*)d_in[14], (const float*)d_in[15],
        (float*)d_out, E);
}

// round 8
// speedup vs baseline: 1.1105x; 1.1105x over previous
#include <cuda_runtime.h>
#include <cuda_fp16.h>
#include <math.h>
#include <stdint.h>

// ============================================================================
// EdgeDecoder, HMMA m16n8k16 fp16 single-term (fp32 accum).
// Round 8: resident fp16 weights in SMEM (no ring, no cp.async in loop),
// one 512-thread CTA/SM split into two warp-groups on alternate tiles with
// named barriers -> phase-shifted overlap of gather/epilogue vs MMA.
// ============================================================================

#define NTH 512

// packed fp16 weights, fragment order:
// [type][ks][ntpair8][lane32][w4]  w: {nt_even b0, nt_even b1, nt_odd b0, nt_odd b1}
__device__ __align__(128) uint32_t g_wbi_pack[32768];   // 2 x 16ks x 8 x 32 x 4
__device__ __align__(128) uint32_t g_w1_pack[16384];    // 2 x 8ks  x 8 x 32 x 4

// ---- SMEM layout (bytes) ----
constexpr int OFF_WBI  = 0;         // resident Wbi frags: 16ks x 8ntp x 512 = 65536
constexpr int OFF_W1   = 65536;     // resident W1 frags:  8ks x 8ntp x 512 = 32768
constexpr int OFF_A    = 98304;     // per-group A: [mt8][ks8]*512 = 32768, x2 groups
constexpr int OFF_SOFF = 163840;    // per-group u32[256], x2
constexpr int OFF_BBI  = 165888;    // f32[128]
constexpr int OFF_B1   = 166400;
constexpr int OFF_W2   = 166912;
constexpr int OFF_PART = 167424;    // per-group f32[256], x2
constexpr int SMEM_TOTAL = 169472;

#define CPA(dst, src) \
    asm volatile("cp.async.cg.shared.global [%0], [%1], 16;" :: "r"(dst), "l"(src))
#define CPA_COMMIT() asm volatile("cp.async.commit_group;" ::: "memory")
#define CPA_WAIT(n)  asm volatile("cp.async.wait_group %0;" :: "n"(n) : "memory")
// group-scoped named barrier (256 threads)
#define BARG(id) asm volatile("bar.sync %0, 256;" :: "r"(id) : "memory")

__device__ __forceinline__ uint32_t smem_to_u32(const void* p) {
    uint32_t a;
    asm("{ .reg .u64 t; cvta.to.shared.u64 t, %1; cvt.u32.u64 %0, t; }" : "=r"(a) : "l"(p));
    return a;
}

__device__ __forceinline__ void mma_f16(float c[4], const uint32_t a[4],
                                        uint32_t b0, uint32_t b1) {
    asm volatile(
        "mma.sync.aligned.m16n8k16.row.col.f32.f16.f16.f32 "
        "{%0,%1,%2,%3}, {%4,%5,%6,%7}, {%8,%9}, {%0,%1,%2,%3};"
        : "+f"(c[0]), "+f"(c[1]), "+f"(c[2]), "+f"(c[3])
        : "r"(a[0]), "r"(a[1]), "r"(a[2]), "r"(a[3]), "r"(b0), "r"(b1));
}

__device__ __forceinline__ float eluf(float x) { return x > 0.f ? x : (__expf(x) - 1.f); }

__device__ __forceinline__ uint32_t pack_h2(float a, float b) {
    __half2 h = __floats2half2_rn(a, b);
    return *(uint32_t*)&h;
}

// ============================================================================
// Pre-pack: fp32 weights -> fp16 frag-order lines, 2 nt per 16B line.
// B frag (m16n8k16 col): b_r = {W[k0+2t+8r][n], W[k0+2t+1+8r][n]}, n = nt*8+g.
// ============================================================================
__global__ void pack_weights_kernel(
    const float* __restrict__ Wbi_ui, const float* __restrict__ W1_ui,
    const float* __restrict__ Wbi_iu, const float* __restrict__ W1_iu)
{
    int id = blockIdx.x * blockDim.x + threadIdx.x;
    const float* W;
    uint32_t* dst;
    int w, lane, ntp, ks;
    if (id < 32768) {
        w = id & 3; lane = (id >> 2) & 31; ntp = (id >> 7) & 7;
        ks = (id >> 10) & 15;
        int type = (id >> 14) & 1;
        W = type ? Wbi_iu : Wbi_ui;
        dst = g_wbi_pack + id;
    } else {
        int id2 = id - 32768;
        if (id2 >= 16384) return;
        w = id2 & 3; lane = (id2 >> 2) & 31; ntp = (id2 >> 7) & 7;
        ks = (id2 >> 10) & 7;
        int type = (id2 >> 13) & 1;
        W = type ? W1_iu : W1_ui;
        dst = g_w1_pack + id2;
    }
    int nt = ntp * 2 + (w >> 1), r = w & 1;
    int k = ks * 16 + (lane & 3) * 2 + r * 8;
    int n = nt * 8 + (lane >> 2);
    *dst = pack_h2(W[k * 128 + n], W[(k + 1) * 128 + n]);
}

// one ks step for one warp: 2 A LDS.128 + 4 B LDS.128 + 16 HMMA
// A buffer has 8 slots per mt; B line = weight region + ks*4096.
__device__ __forceinline__ void mma_step(
    const char* smA, const char* smB_ks, int slotA, int mi, int ni, int l16,
    float C[2][8][4])
{
    uint4 A0 = *(const uint4*)(smA + ((mi * 2 + 0) * 8 + slotA) * 512 + l16);
    uint4 A1 = *(const uint4*)(smA + ((mi * 2 + 1) * 8 + slotA) * 512 + l16);
    #pragma unroll
    for (int p = 0; p < 4; p++) {
        uint4 B = *(const uint4*)(smB_ks + (ni * 4 + p) * 512 + l16);
        mma_f16(C[0][2 * p],     &A0.x, B.x, B.y);
        mma_f16(C[1][2 * p],     &A1.x, B.x, B.y);
        mma_f16(C[0][2 * p + 1], &A0.x, B.z, B.w);
        mma_f16(C[1][2 * p + 1], &A1.x, B.z, B.w);
    }
}

// gather one 128-K half for 128 edges into the group's 8 A slots
__device__ __forceinline__ void gather_half(
    char* smA, const float* eb, const uint32_t* sOffH, int wid8, int lane, int l16)
{
    const int g = lane >> 2, t = lane & 3;
    const int mt = wid8;
    const uint32_t o0 = sOffH[mt * 16 + g];
    const uint32_t o1 = sOffH[mt * 16 + g + 8];
    #pragma unroll
    for (int ks = 0; ks < 8; ks++) {
        const int kf = ks * 16 + 2 * t;
        float2 p00 = *(const float2*)(eb + o0 + kf);
        float2 p01 = *(const float2*)(eb + o0 + kf + 8);
        float2 p10 = *(const float2*)(eb + o1 + kf);
        float2 p11 = *(const float2*)(eb + o1 + kf + 8);
        uint4 hi;
        hi.x = pack_h2(p00.x, p00.y);
        hi.y = pack_h2(p10.x, p10.y);
        hi.z = pack_h2(p01.x, p01.y);
        hi.w = pack_h2(p11.x, p11.y);
        *(uint4*)(smA + (mt * 8 + ks) * 512 + l16) = hi;
    }
}

__global__ __launch_bounds__(NTH, 1)
void edge_decoder_mma(
    const float* __restrict__ user_emb, const float* __restrict__ item_emb,
    const void* __restrict__ ei_ui, const void* __restrict__ ei_iu,
    const float* __restrict__ bbi_ui, const float* __restrict__ b1_ui,
    const float* __restrict__ W2_ui,  const float* __restrict__ b2_ui,
    const float* __restrict__ bbi_iu, const float* __restrict__ b1_iu,
    const float* __restrict__ W2_iu,  const float* __restrict__ b2_iu,
    float* __restrict__ out, int E)
{
    extern __shared__ char sm[];
    const uint32_t sm_u32 = smem_to_u32(sm);
    const int tid   = threadIdx.x;
    const int group = tid >> 8;          // 0 or 1
    const int gtid  = tid & 255;
    const int wid8  = gtid >> 5;         // warp in group (0..7)
    const int lane  = tid & 31;
    const int mi    = wid8 & 3;          // 32-row group
    const int ni    = wid8 >> 2;         // 64-col group
    const int g     = lane >> 2;
    const int t     = lane & 3;
    const int l16   = lane * 16;
    const int barid = 1 + group;

    const int type  = blockIdx.x & 1;
    const int slot0 = blockIdx.x >> 1;   // 0..147

    const float* srcE = type ? item_emb : user_emb;
    const float* dstE = type ? user_emb : item_emb;
    const void*  ei   = type ? ei_iu : ei_ui;
    const float* bbi  = type ? bbi_iu : bbi_ui;
    const float* b1   = type ? b1_iu : b1_ui;
    const float* W2   = type ? W2_iu : W2_ui;
    const float* b2   = type ? b2_iu : b2_ui;
    const uint32_t* wbiP = g_wbi_pack + (size_t)type * 16384;
    const uint32_t* w1P  = g_w1_pack  + (size_t)type * 8192;

    float*    sBbi  = (float*)(sm + OFF_BBI);
    float*    sB1   = (float*)(sm + OFF_B1);
    float*    sW2   = (float*)(sm + OFF_W2);
    float*    sPart = (float*)(sm + OFF_PART) + group * 256;
    uint32_t* sOff  = (uint32_t*)(sm + OFF_SOFF) + group * 256;
    char*     smA   = sm + OFF_A + group * 32768;
    const char* smWbi = sm + OFF_WBI;
    const char* smW1  = sm + OFF_W1;

    // ---- one-time: resident weights via cp.async (all 512 threads) ----
    #pragma unroll
    for (int q = 0; q < 8; q++)
        CPA(sm_u32 + OFF_WBI + (uint32_t)(tid + q * 512) * 16, wbiP + (tid + q * 512) * 4);
    #pragma unroll
    for (int q = 0; q < 4; q++)
        CPA(sm_u32 + OFF_W1 + (uint32_t)(tid + q * 512) * 16, w1P + (tid + q * 512) * 4);
    CPA_COMMIT();

    bool is64;
    {
        const int* w = (const int*)ei_ui;
        int all0 = 1;
        #pragma unroll
        for (int k = 0; k < 8; k++) all0 &= (w[2 * k + 1] == 0);
        is64 = (all0 != 0);
    }
    const float b2v = b2[0];
    if (tid < 128) {
        sBbi[tid] = bbi[tid];
        sB1[tid]  = b1[tid];
        sW2[tid]  = W2[tid];
    }
    CPA_WAIT(0);
    __syncthreads();                     // weights + biases resident

    const int ntiles = (E + 127) / 128;

    // group g handles tiles slot0 + (2j+g)*148
    for (int tile = slot0 + group * 148; tile < ntiles; tile += 296) {
        const int base = tile * 128;

        // ---- indices for this group's tile ----
        {
            const int half = gtid >> 7, e = gtid & 127, ge = base + e;
            uint32_t off = 0;
            if (ge < E) {
                long long idx = is64 ? ((const long long*)ei)[half ? (E + ge) : ge]
                                     : (long long)((const int*)ei)[half ? (E + ge) : ge];
                off = (uint32_t)idx << 7;
            }
            sOff[gtid] = off;
        }
        BARG(barid);                     // sOff ready; prev-tile A reads done

        // ---- gather src half; GEMM1a (ks 0..7) ----
        gather_half(smA, srcE, sOff, wid8, lane, l16);
        BARG(barid);

        float C[2][8][4];
        #pragma unroll
        for (int m = 0; m < 2; m++)
            #pragma unroll
            for (int a = 0; a < 8; a++)
                #pragma unroll
                for (int b = 0; b < 4; b++) C[m][a][b] = 0.f;

        #pragma unroll
        for (int ks = 0; ks < 8; ks++)
            mma_step(smA, smWbi + ks * 4096, ks, mi, ni, l16, C);
        BARG(barid);                     // A consumed

        // ---- gather dst half; GEMM1b (ks 8..15) ----
        gather_half(smA, dstE, sOff + 128, wid8, lane, l16);
        BARG(barid);

        #pragma unroll
        for (int ks = 8; ks < 16; ks++)
            mma_step(smA, smWbi + ks * 4096, ks - 8, mi, ni, l16, C);
        BARG(barid);                     // A consumed

        // ---- epilogue1: ELU(C+bbi) -> fp16 -> A2 slots (ni*4 + 0..3) ----
        #pragma unroll
        for (int mtl = 0; mtl < 2; mtl++) {
            #pragma unroll
            for (int s = 0; s < 4; s++) {
                uint4 hi;
                int col = ni * 64 + (2 * s) * 8 + 2 * t;
                {
                    const float bb0 = sBbi[col], bb1 = sBbi[col + 1];
                    hi.x = pack_h2(eluf(C[mtl][2 * s][0] + bb0), eluf(C[mtl][2 * s][1] + bb1));
                    hi.y = pack_h2(eluf(C[mtl][2 * s][2] + bb0), eluf(C[mtl][2 * s][3] + bb1));
                }
                col += 8;
                {
                    const float bb0 = sBbi[col], bb1 = sBbi[col + 1];
                    hi.z = pack_h2(eluf(C[mtl][2 * s + 1][0] + bb0), eluf(C[mtl][2 * s + 1][1] + bb1));
                    hi.w = pack_h2(eluf(C[mtl][2 * s + 1][2] + bb0), eluf(C[mtl][2 * s + 1][3] + bb1));
                }
                const int mt2 = mi * 2 + mtl;
                *(uint4*)(smA + (mt2 * 8 + ni * 4 + s) * 512 + l16) = hi;
            }
        }
        BARG(barid);                     // A2 ready

        // ---- GEMM2 (ks 0..7, resident W1) ----
        float C2[2][8][4];
        #pragma unroll
        for (int m = 0; m < 2; m++)
            #pragma unroll
            for (int a = 0; a < 8; a++)
                #pragma unroll
                for (int b = 0; b < 4; b++) C2[m][a][b] = 0.f;

        #pragma unroll
        for (int ks = 0; ks < 8; ks++)
            mma_step(smA, smW1 + ks * 4096, ks, mi, ni, l16, C2);

        // ---- epilogue2: ELU(C2+b1) . W2, quad reduce, sigmoid ----
        #pragma unroll
        for (int mtl = 0; mtl < 2; mtl++) {
            float r0 = 0.f, r1 = 0.f;
            #pragma unroll
            for (int ntl = 0; ntl < 8; ntl++) {
                const int col = ni * 64 + ntl * 8 + 2 * t;
                const float w0 = sW2[col], w1 = sW2[col + 1];
                const float bb0 = sB1[col], bb1 = sB1[col + 1];
                r0 += eluf(C2[mtl][ntl][0] + bb0) * w0 + eluf(C2[mtl][ntl][1] + bb1) * w1;
                r1 += eluf(C2[mtl][ntl][2] + bb0) * w0 + eluf(C2[mtl][ntl][3] + bb1) * w1;
            }
            r0 += __shfl_xor_sync(0xffffffffu, r0, 1);
            r1 += __shfl_xor_sync(0xffffffffu, r1, 1);
            r0 += __shfl_xor_sync(0xffffffffu, r0, 2);
            r1 += __shfl_xor_sync(0xffffffffu, r1, 2);
            if (t == 0) {
                const int m = (mi * 2 + mtl) * 16 + g;
                sPart[ni * 128 + m]     = r0;
                sPart[ni * 128 + m + 8] = r1;
            }
        }
        BARG(barid);                     // sPart ready; GEMM2 reads done

        if (gtid < 128) {
            const int ge = base + gtid;
            if (ge < E) {
                float s = sPart[gtid] + sPart[128 + gtid] + b2v;
                out[(size_t)type * E + ge] = 1.f / (1.f + __expf(-s));
            }
        }
    }
}

extern "C" void kernel_launch(void* const* d_in, const int* in_sizes, int n_in,
                              void* d_out, int out_size) {
    (void)n_in; (void)out_size;
    const int E = in_sizes[2] / 2;
    pack_weights_kernel<<<96, 512>>>(
        (const float*)d_in[4], (const float*)d_in[6],
        (const float*)d_in[10], (const float*)d_in[12]);
    cudaFuncSetAttribute(edge_decoder_mma,
                         cudaFuncAttributeMaxDynamicSharedMemorySize, SMEM_TOTAL);
    edge_decoder_mma<<<296, NTH, SMEM_TOTAL>>>(
        (const float*)d_in[0],  (const float*)d_in[1],
        d_in[2], d_in[3],
        (const float*)d_in[5],  (const float*)d_in[7],
        (const float*)d_in[8],  (const float*)d_in[9],
        (const float*)d_in[11], (const float*)d_in[13],
        (const float*)d_in[14], (const float*)d_in[15],
        (float*)d_out, E);
}